// round 7
// baseline (speedup 1.0000x reference)
#include <cuda_runtime.h>
#include <cuda_fp16.h>
#include <math.h>

#define NN   100000
#define EE   1600000
#define FIN  128
#define FOUT 64
#define THRESH 0.48f
#define MAXN   (1.0f - 4e-3f)

#define SCAN_B 1024
#define NBLK   ((NN + SCAN_B - 1) / SCAN_B)   // 98

#define GEMM_ROWS   32
#define GEMM_BLOCKS (NN / GEMM_ROWS)          // 3125
#define ZERO_BLOCKS ((NN + 255) / 256)        // 391

typedef unsigned long long u64;

// -------- scratch (device globals; no allocation allowed) --------
__device__ float   g_updated [NN * FOUT];
__device__ __half2 g_uhalf   [NN * 32];       // fp16 mirror for passes B/C
__device__ float   g_sumneigh[NN * FOUT];
__device__ float   g_sel     [NN];
__device__ float   g_gate    [NN];
__device__ int     g_rowptr  [NN + 1];
__device__ int     g_cursor  [NN];
__device__ int     g_col     [EE];
__device__ int     g_blocksum[NBLK];
__device__ int     g_blockoff[NBLK];

// ---- f32x2 helpers ----
__device__ __forceinline__ u64 pack2(float lo, float hi) {
    u64 r; asm("mov.b64 %0,{%1,%2};" : "=l"(r) : "f"(lo), "f"(hi)); return r;
}
__device__ __forceinline__ void unpack2(u64 v, float& lo, float& hi) {
    asm("mov.b64 {%0,%1},%2;" : "=f"(lo), "=f"(hi) : "l"(v));
}
__device__ __forceinline__ u64 add2(u64 a, u64 b) {
    u64 d; asm("add.rn.f32x2 %0,%1,%2;" : "=l"(d) : "l"(a), "l"(b)); return d;
}
__device__ __forceinline__ u64 fma2(u64 a, u64 b, u64 c) {
    u64 d; asm("fma.rn.f32x2 %0,%1,%2,%3;" : "=l"(d) : "l"(a), "l"(b), "l"(c)); return d;
}

// ---------------------------------------------------------------------------
// K1: logmap0 + GEMM (x_tan @ W_up) + leaky_relu -> g_updated (+fp16 mirror).
// 32 rows/block, f32x2 FMAs, 2 rows/thread. Trailing blocks zero g_cursor.
// ---------------------------------------------------------------------------
__global__ void __launch_bounds__(256) k_up(const float* __restrict__ x,
                                            const float* __restrict__ Wup) {
    if (blockIdx.x >= GEMM_BLOCKS) {
        int i = (blockIdx.x - GEMM_BLOCKS) * 256 + threadIdx.x;
        if (i < NN) g_cursor[i] = 0;
        return;
    }
    __shared__ float  xs[GEMM_ROWS][FIN];
    __shared__ float4 Ws[FIN * 16];
    __shared__ float  sscale[GEMM_ROWS];

    int t = threadIdx.x;
    int rbase = blockIdx.x * GEMM_ROWS;

    const float4* W4 = (const float4*)Wup;
    #pragma unroll
    for (int i = t; i < FIN * 16; i += 256) Ws[i] = W4[i];
    #pragma unroll
    for (int i = t; i < GEMM_ROWS * FIN; i += 256)
        xs[i >> 7][i & 127] = x[(size_t)rbase * FIN + i];
    __syncthreads();

    int w = t >> 5, lane = t & 31;
    #pragma unroll
    for (int rr = 0; rr < 4; ++rr) {
        int r = w * 4 + rr;
        float v0 = xs[r][lane], v1 = xs[r][lane + 32];
        float v2 = xs[r][lane + 64], v3 = xs[r][lane + 96];
        float s = v0 * v0 + v1 * v1 + v2 * v2 + v3 * v3;
        #pragma unroll
        for (int o = 16; o; o >>= 1) s += __shfl_xor_sync(0xffffffffu, s, o);
        if (lane == 0) {
            float n = fmaxf(sqrtf(s), 1e-15f);
            float a = fminf(fmaxf(n, -1.0f + 1e-7f), 1.0f - 1e-7f);
            float art = 0.5f * (log1pf(a) - log1pf(-a));
            sscale[r] = art / n;
        }
    }
    __syncthreads();

    int rp = t >> 4;
    int cg = t & 15;
    int r0 = rp, r1 = rp + 16;
    u64 a00 = 0, a01 = 0, a10 = 0, a11 = 0;

    #pragma unroll 4
    for (int k = 0; k < FIN; ++k) {
        float4 wv = Ws[k * 16 + cg];
        u64 w01 = pack2(wv.x, wv.y);
        u64 w23 = pack2(wv.z, wv.w);
        float xv0 = xs[r0][k], xv1 = xs[r1][k];
        u64 xa = pack2(xv0, xv0);
        u64 xb = pack2(xv1, xv1);
        a00 = fma2(xa, w01, a00);
        a01 = fma2(xa, w23, a01);
        a10 = fma2(xb, w01, a10);
        a11 = fma2(xb, w23, a11);
    }

    #pragma unroll
    for (int rr = 0; rr < 2; ++rr) {
        int r = rr ? r1 : r0;
        float sc = sscale[r];
        float c0, c1, c2, c3;
        unpack2(rr ? a10 : a00, c0, c1);
        unpack2(rr ? a11 : a01, c2, c3);
        float4 o;
        float v;
        v = c0 * sc; o.x = v > 0.f ? v : 0.01f * v;
        v = c1 * sc; o.y = v > 0.f ? v : 0.01f * v;
        v = c2 * sc; o.z = v > 0.f ? v : 0.01f * v;
        v = c3 * sc; o.w = v > 0.f ? v : 0.01f * v;
        size_t ro = (size_t)(rbase + r);
        ((float4*)g_updated)[ro * 16 + cg] = o;
        g_uhalf[ro * 32 + cg * 2    ] = __floats2half2_rn(o.x, o.y);
        g_uhalf[ro * 32 + cg * 2 + 1] = __floats2half2_rn(o.z, o.w);
    }
}

// ---------------------------------------------------------------------------
// CSR build
// ---------------------------------------------------------------------------
__global__ void k_hist(const int* __restrict__ ei) {
    int t = blockIdx.x * blockDim.x + threadIdx.x;
    if (t < EE) atomicAdd(&g_cursor[ei[EE + t]], 1);
}

__global__ void __launch_bounds__(SCAN_B) k_scan1() {
    __shared__ int wsum[32];
    int t = threadIdx.x, b = blockIdx.x;
    int idx = b * SCAN_B + t;
    int lane = t & 31, w = t >> 5;
    int c = (idx < NN) ? g_cursor[idx] : 0;
    int v = c;
    #pragma unroll
    for (int o = 1; o < 32; o <<= 1) {
        int n = __shfl_up_sync(0xffffffffu, v, o);
        if (lane >= o) v += n;
    }
    if (lane == 31) wsum[w] = v;
    __syncthreads();
    if (w == 0) {
        int s = wsum[lane];
        #pragma unroll
        for (int o = 1; o < 32; o <<= 1) {
            int n = __shfl_up_sync(0xffffffffu, s, o);
            if (lane >= o) s += n;
        }
        wsum[lane] = s;
    }
    __syncthreads();
    int base = (w > 0) ? wsum[w - 1] : 0;
    int incl = v + base;
    if (idx < NN) g_rowptr[idx] = incl - c;
    if (t == SCAN_B - 1) g_blocksum[b] = incl;
}

__global__ void __launch_bounds__(128) k_scan2() {
    __shared__ int s[128];
    int t = threadIdx.x;
    int v = (t < NBLK) ? g_blocksum[t] : 0;
    s[t] = v;
    __syncthreads();
    #pragma unroll
    for (int o = 1; o < 128; o <<= 1) {
        int a = (t >= o) ? s[t - o] : 0;
        __syncthreads();
        s[t] += a;
        __syncthreads();
    }
    if (t < NBLK) g_blockoff[t] = s[t] - v;
}

__global__ void __launch_bounds__(SCAN_B) k_scan3() {
    int idx = blockIdx.x * SCAN_B + threadIdx.x;
    if (idx < NN) {
        int r = g_rowptr[idx] + g_blockoff[blockIdx.x];
        g_rowptr[idx] = r;
        g_cursor[idx] = r;
    }
    if (idx == 0) g_rowptr[NN] = EE;
}

__global__ void k_fill(const int* __restrict__ ei) {
    int t = blockIdx.x * blockDim.x + threadIdx.x;
    if (t < EE) {
        int d = ei[EE + t];
        int p = atomicAdd(&g_cursor[d], 1);
        g_col[p] = ei[t];
    }
}

// ---------------------------------------------------------------------------
// Pass A: fp32 gather (feeds hard threshold) + fused sel gate
// ---------------------------------------------------------------------------
__global__ void __launch_bounds__(256) k_aggA(const float* __restrict__ Wpl) {
    int gw = (blockIdx.x * blockDim.x + threadIdx.x) >> 5;
    int lane = threadIdx.x & 31;
    if (gw >= NN) return;
    int s = g_rowptr[gw], e = g_rowptr[gw + 1];
    const u64* U = (const u64*)g_updated;
    u64 acc0 = 0, acc1 = 0;
    int p = s;
    for (; p + 4 <= e; p += 4) {
        int j0 = __ldg(&g_col[p]);
        int j1 = __ldg(&g_col[p + 1]);
        int j2 = __ldg(&g_col[p + 2]);
        int j3 = __ldg(&g_col[p + 3]);
        u64 u0 = __ldg(&U[(size_t)j0 * 32 + lane]);
        u64 u1 = __ldg(&U[(size_t)j1 * 32 + lane]);
        u64 u2 = __ldg(&U[(size_t)j2 * 32 + lane]);
        u64 u3 = __ldg(&U[(size_t)j3 * 32 + lane]);
        acc0 = add2(acc0, u0);
        acc1 = add2(acc1, u1);
        acc0 = add2(acc0, u2);
        acc1 = add2(acc1, u3);
    }
    for (; p < e; ++p) {
        int j = __ldg(&g_col[p]);
        acc0 = add2(acc0, __ldg(&U[(size_t)j * 32 + lane]));
    }
    u64 accp = add2(acc0, acc1);
    float ax, ay; unpack2(accp, ax, ay);
    ((float2*)g_sumneigh)[(size_t)gw * 32 + lane] = make_float2(ax, ay);

    float4 wp = ((const float4*)Wpl)[lane];
    float a0 = ax * wp.x + ay * wp.z;
    float a1 = ax * wp.y + ay * wp.w;
    #pragma unroll
    for (int o = 16; o; o >>= 1) {
        a0 += __shfl_xor_sync(0xffffffffu, a0, o);
        a1 += __shfl_xor_sync(0xffffffffu, a1, o);
    }
    if (lane == 0) {
        float r0 = fmaxf(a0, 0.f), r1 = fmaxf(a1, 0.f);
        float p1 = 1.0f / (1.0f + expf(r0 - r1));
        g_sel[gw] = (p1 > THRESH) ? 1.0f : 0.0f;
    }
}

// ---------------------------------------------------------------------------
// Pass B: fp16 gather of selected neighbors -> gate
// ---------------------------------------------------------------------------
__global__ void __launch_bounds__(256) k_aggB(const float* __restrict__ Wlw) {
    int gw = (blockIdx.x * blockDim.x + threadIdx.x) >> 5;
    int lane = threadIdx.x & 31;
    if (gw >= NN) return;
    int s = g_rowptr[gw], e = g_rowptr[gw + 1];
    const __half2* U = g_uhalf;
    float2 acc0 = make_float2(0.f, 0.f), acc1 = make_float2(0.f, 0.f);
    int p = s;
    for (; p + 4 <= e; p += 4) {
        int j0 = __ldg(&g_col[p]);
        int j1 = __ldg(&g_col[p + 1]);
        int j2 = __ldg(&g_col[p + 2]);
        int j3 = __ldg(&g_col[p + 3]);
        float s0 = __ldg(&g_sel[j0]), s1 = __ldg(&g_sel[j1]);
        float s2 = __ldg(&g_sel[j2]), s3 = __ldg(&g_sel[j3]);
        if (s0 != 0.f) { float2 u = __half22float2(__ldg(&U[(size_t)j0 * 32 + lane])); acc0.x += u.x; acc0.y += u.y; }
        if (s1 != 0.f) { float2 u = __half22float2(__ldg(&U[(size_t)j1 * 32 + lane])); acc1.x += u.x; acc1.y += u.y; }
        if (s2 != 0.f) { float2 u = __half22float2(__ldg(&U[(size_t)j2 * 32 + lane])); acc0.x += u.x; acc0.y += u.y; }
        if (s3 != 0.f) { float2 u = __half22float2(__ldg(&U[(size_t)j3 * 32 + lane])); acc1.x += u.x; acc1.y += u.y; }
    }
    for (; p < e; ++p) {
        int j = __ldg(&g_col[p]);
        if (__ldg(&g_sel[j]) != 0.f) {
            float2 u = __half22float2(__ldg(&U[(size_t)j * 32 + lane]));
            acc0.x += u.x; acc0.y += u.y;
        }
    }
    float ax = acc0.x + acc1.x, ay = acc0.y + acc1.y;
    float2 sn = ((const float2*)g_sumneigh)[(size_t)gw * 32 + lane];
    float2 wl0 = ((const float2*)Wlw)[lane];
    float2 wl1 = ((const float2*)Wlw)[32 + lane];
    float z = ax * wl0.x + ay * wl0.y + sn.x * wl1.x + sn.y * wl1.y;
    #pragma unroll
    for (int o = 16; o; o >>= 1) z += __shfl_xor_sync(0xffffffffu, z, o);
    if (lane == 0) {
        float ws = 1.0f / (1.0f + expf(-z));
        g_gate[gw] = ws * g_sel[gw];
    }
}

// ---------------------------------------------------------------------------
// Pass C: fp16 gated gather; epilogue in fp32 (u_i read fp32)
// ---------------------------------------------------------------------------
__global__ void __launch_bounds__(256) k_aggC(float* __restrict__ out) {
    int gw = (blockIdx.x * blockDim.x + threadIdx.x) >> 5;
    int lane = threadIdx.x & 31;
    if (gw >= NN) return;
    int s = g_rowptr[gw], e = g_rowptr[gw + 1];
    const __half2* U = g_uhalf;
    float2 acc0 = make_float2(0.f, 0.f), acc1 = make_float2(0.f, 0.f);
    int p = s;
    for (; p + 4 <= e; p += 4) {
        int j0 = __ldg(&g_col[p]);
        int j1 = __ldg(&g_col[p + 1]);
        int j2 = __ldg(&g_col[p + 2]);
        int j3 = __ldg(&g_col[p + 3]);
        float g0 = __ldg(&g_gate[j0]), g1 = __ldg(&g_gate[j1]);
        float g2 = __ldg(&g_gate[j2]), g3 = __ldg(&g_gate[j3]);
        if (g0 != 0.f) { float2 u = __half22float2(__ldg(&U[(size_t)j0 * 32 + lane])); acc0.x = fmaf(g0, u.x, acc0.x); acc0.y = fmaf(g0, u.y, acc0.y); }
        if (g1 != 0.f) { float2 u = __half22float2(__ldg(&U[(size_t)j1 * 32 + lane])); acc1.x = fmaf(g1, u.x, acc1.x); acc1.y = fmaf(g1, u.y, acc1.y); }
        if (g2 != 0.f) { float2 u = __half22float2(__ldg(&U[(size_t)j2 * 32 + lane])); acc0.x = fmaf(g2, u.x, acc0.x); acc0.y = fmaf(g2, u.y, acc0.y); }
        if (g3 != 0.f) { float2 u = __half22float2(__ldg(&U[(size_t)j3 * 32 + lane])); acc1.x = fmaf(g3, u.x, acc1.x); acc1.y = fmaf(g3, u.y, acc1.y); }
    }
    for (; p < e; ++p) {
        int j = __ldg(&g_col[p]);
        float g = __ldg(&g_gate[j]);
        if (g != 0.f) {
            float2 u = __half22float2(__ldg(&U[(size_t)j * 32 + lane]));
            acc0.x = fmaf(g, u.x, acc0.x); acc0.y = fmaf(g, u.y, acc0.y);
        }
    }
    float ax = acc0.x + acc1.x, ay = acc0.y + acc1.y;
    float2 ui = ((const float2*)g_updated)[(size_t)gw * 32 + lane];
    float ox = ui.x + fmaxf(ax, 0.f);
    float oy = ui.y + fmaxf(ay, 0.f);
    float ss = ox * ox + oy * oy;
    #pragma unroll
    for (int o = 16; o; o >>= 1) ss += __shfl_xor_sync(0xffffffffu, ss, o);
    float n = fmaxf(sqrtf(ss), 1e-15f);
    float th = tanhf(n);
    float f = (th > MAXN) ? (MAXN / n) : (th / n);
    ((float2*)out)[(size_t)gw * 32 + lane] = make_float2(ox * f, oy * f);
}

// ---------------------------------------------------------------------------
extern "C" void kernel_launch(void* const* d_in, const int* in_sizes, int n_in,
                              void* d_out, int out_size) {
    const float* x   = (const float*)d_in[0];
    const int*   ei  = (const int*)  d_in[1];
    const float* Wup = (const float*)d_in[2];
    const float* Wpl = (const float*)d_in[3];
    const float* Wlw = (const float*)d_in[4];
    float* out = (float*)d_out;

    (void)in_sizes; (void)n_in; (void)out_size;

    k_up<<<GEMM_BLOCKS + ZERO_BLOCKS, 256>>>(x, Wup);

    k_hist<<<(EE + 255) / 256, 256>>>(ei);
    k_scan1<<<NBLK, SCAN_B>>>();
    k_scan2<<<1, 128>>>();
    k_scan3<<<NBLK, SCAN_B>>>();
    k_fill<<<(EE + 255) / 256, 256>>>(ei);

    int aggBlocks = (NN * 32 + 255) / 256;
    k_aggA<<<aggBlocks, 256>>>(Wpl);
    k_aggB<<<aggBlocks, 256>>>(Wlw);
    k_aggC<<<aggBlocks, 256>>>(out);
}

// round 8
// speedup vs baseline: 1.2099x; 1.2099x over previous
#include <cuda_runtime.h>
#include <math.h>

#define NN   100000
#define EE   1600000
#define FIN  128
#define FOUT 64
#define THRESH 0.48f
#define MAXN   (1.0f - 4e-3f)

#define SCAN_B 1024
#define NBLK   ((NN + SCAN_B - 1) / SCAN_B)   // 98

#define GEMM_ROWS   32
#define GEMM_BLOCKS (NN / GEMM_ROWS)          // 3125
#define ZERO_BLOCKS ((NN + 255) / 256)        // 391

typedef unsigned long long u64;

// -------- scratch (device globals; no allocation allowed) --------
__device__ float  g_updated [NN * FOUT];
__device__ float4 g_e       [NN];   // (u.wpl0, u.wpl1, u.wlw_hi, u.wlw_lo)
__device__ float  g_b1      [NN];   // sum_j dot(u[j], wlw_hi)
__device__ float  g_sel     [NN];   // 0/1 hard gate
__device__ float  g_selD    [NN];   // sel * dot(u, wlw_lo)
__device__ float  g_gate    [NN];   // weight_sel * sel
__device__ int    g_rowptr  [NN + 1];
__device__ int    g_cursor  [NN];
__device__ int    g_col     [EE];
__device__ int    g_blocksum[NBLK];
__device__ int    g_blockoff[NBLK];

// ---- f32x2 helpers ----
__device__ __forceinline__ u64 pack2(float lo, float hi) {
    u64 r; asm("mov.b64 %0,{%1,%2};" : "=l"(r) : "f"(lo), "f"(hi)); return r;
}
__device__ __forceinline__ void unpack2(u64 v, float& lo, float& hi) {
    asm("mov.b64 {%0,%1},%2;" : "=f"(lo), "=f"(hi) : "l"(v));
}
__device__ __forceinline__ u64 add2(u64 a, u64 b) {
    u64 d; asm("add.rn.f32x2 %0,%1,%2;" : "=l"(d) : "l"(a), "l"(b)); return d;
}
__device__ __forceinline__ u64 fma2(u64 a, u64 b, u64 c) {
    u64 d; asm("fma.rn.f32x2 %0,%1,%2,%3;" : "=l"(d) : "l"(a), "l"(b), "l"(c)); return d;
}

// ---------------------------------------------------------------------------
// K1: logmap0 + GEMM + leaky_relu -> g_updated; epilogue computes per-node
// projection float4 g_e. Trailing blocks zero g_cursor.
// ---------------------------------------------------------------------------
__global__ void __launch_bounds__(256) k_up(const float* __restrict__ x,
                                            const float* __restrict__ Wup,
                                            const float* __restrict__ Wpl,
                                            const float* __restrict__ Wlw) {
    if (blockIdx.x >= GEMM_BLOCKS) {
        int i = (blockIdx.x - GEMM_BLOCKS) * 256 + threadIdx.x;
        if (i < NN) g_cursor[i] = 0;
        return;
    }
    __shared__ float  xs[GEMM_ROWS][FIN];
    __shared__ float4 Ws[FIN * 16];
    __shared__ float  sscale[GEMM_ROWS];
    __shared__ float4 sWe[FOUT];     // per-col (wpl0, wpl1, wlw_hi, wlw_lo)

    int t = threadIdx.x;
    int rbase = blockIdx.x * GEMM_ROWS;

    const float4* W4 = (const float4*)Wup;
    #pragma unroll
    for (int i = t; i < FIN * 16; i += 256) Ws[i] = W4[i];
    #pragma unroll
    for (int i = t; i < GEMM_ROWS * FIN; i += 256)
        xs[i >> 7][i & 127] = x[(size_t)rbase * FIN + i];
    if (t < FOUT)
        sWe[t] = make_float4(Wpl[2 * t], Wpl[2 * t + 1], Wlw[64 + t], Wlw[t]);
    __syncthreads();

    int w = t >> 5, lane = t & 31;
    #pragma unroll
    for (int rr = 0; rr < 4; ++rr) {
        int r = w * 4 + rr;
        float v0 = xs[r][lane], v1 = xs[r][lane + 32];
        float v2 = xs[r][lane + 64], v3 = xs[r][lane + 96];
        float s = v0 * v0 + v1 * v1 + v2 * v2 + v3 * v3;
        #pragma unroll
        for (int o = 16; o; o >>= 1) s += __shfl_xor_sync(0xffffffffu, s, o);
        if (lane == 0) {
            float n = fmaxf(sqrtf(s), 1e-15f);
            float a = fminf(fmaxf(n, -1.0f + 1e-7f), 1.0f - 1e-7f);
            float art = 0.5f * (log1pf(a) - log1pf(-a));
            sscale[r] = art / n;
        }
    }
    __syncthreads();

    int rp = t >> 4;          // rows rp, rp+16
    int cg = t & 15;          // col group of 4
    int r0 = rp, r1 = rp + 16;
    u64 a00 = 0, a01 = 0, a10 = 0, a11 = 0;

    #pragma unroll 4
    for (int k = 0; k < FIN; ++k) {
        float4 wv = Ws[k * 16 + cg];
        u64 w01 = pack2(wv.x, wv.y);
        u64 w23 = pack2(wv.z, wv.w);
        float xv0 = xs[r0][k], xv1 = xs[r1][k];
        u64 xa = pack2(xv0, xv0);
        u64 xb = pack2(xv1, xv1);
        a00 = fma2(xa, w01, a00);
        a01 = fma2(xa, w23, a01);
        a10 = fma2(xb, w01, a10);
        a11 = fma2(xb, w23, a11);
    }

    float4 we0 = sWe[cg * 4 + 0], we1 = sWe[cg * 4 + 1];
    float4 we2 = sWe[cg * 4 + 2], we3 = sWe[cg * 4 + 3];

    #pragma unroll
    for (int rr = 0; rr < 2; ++rr) {
        int r = rr ? r1 : r0;
        float sc = sscale[r];
        float c0, c1, c2, c3;
        unpack2(rr ? a10 : a00, c0, c1);
        unpack2(rr ? a11 : a01, c2, c3);
        float4 o;
        float v;
        v = c0 * sc; o.x = v > 0.f ? v : 0.01f * v;
        v = c1 * sc; o.y = v > 0.f ? v : 0.01f * v;
        v = c2 * sc; o.z = v > 0.f ? v : 0.01f * v;
        v = c3 * sc; o.w = v > 0.f ? v : 0.01f * v;
        ((float4*)g_updated)[(size_t)(rbase + r) * 16 + cg] = o;

        // partial projections over this thread's 4 cols
        float d0 = o.x * we0.x + o.y * we1.x + o.z * we2.x + o.w * we3.x;
        float d1 = o.x * we0.y + o.y * we1.y + o.z * we2.y + o.w * we3.y;
        float d2 = o.x * we0.z + o.y * we1.z + o.z * we2.z + o.w * we3.z;
        float d3 = o.x * we0.w + o.y * we1.w + o.z * we2.w + o.w * we3.w;
        #pragma unroll
        for (int off = 8; off; off >>= 1) {   // reduce across 16-thread row group
            d0 += __shfl_xor_sync(0xffffffffu, d0, off);
            d1 += __shfl_xor_sync(0xffffffffu, d1, off);
            d2 += __shfl_xor_sync(0xffffffffu, d2, off);
            d3 += __shfl_xor_sync(0xffffffffu, d3, off);
        }
        if (cg == 0) g_e[rbase + r] = make_float4(d0, d1, d2, d3);
    }
}

// ---------------------------------------------------------------------------
// CSR build
// ---------------------------------------------------------------------------
__global__ void k_hist(const int* __restrict__ ei) {
    int t = blockIdx.x * blockDim.x + threadIdx.x;
    if (t < EE) atomicAdd(&g_cursor[ei[EE + t]], 1);
}

__global__ void __launch_bounds__(SCAN_B) k_scan1() {
    __shared__ int wsum[32];
    int t = threadIdx.x, b = blockIdx.x;
    int idx = b * SCAN_B + t;
    int lane = t & 31, w = t >> 5;
    int c = (idx < NN) ? g_cursor[idx] : 0;
    int v = c;
    #pragma unroll
    for (int o = 1; o < 32; o <<= 1) {
        int n = __shfl_up_sync(0xffffffffu, v, o);
        if (lane >= o) v += n;
    }
    if (lane == 31) wsum[w] = v;
    __syncthreads();
    if (w == 0) {
        int s = wsum[lane];
        #pragma unroll
        for (int o = 1; o < 32; o <<= 1) {
            int n = __shfl_up_sync(0xffffffffu, s, o);
            if (lane >= o) s += n;
        }
        wsum[lane] = s;
    }
    __syncthreads();
    int base = (w > 0) ? wsum[w - 1] : 0;
    int incl = v + base;
    if (idx < NN) g_rowptr[idx] = incl - c;
    if (t == SCAN_B - 1) g_blocksum[b] = incl;
}

__global__ void __launch_bounds__(128) k_scan2() {
    __shared__ int s[128];
    int t = threadIdx.x;
    int v = (t < NBLK) ? g_blocksum[t] : 0;
    s[t] = v;
    __syncthreads();
    #pragma unroll
    for (int o = 1; o < 128; o <<= 1) {
        int a = (t >= o) ? s[t - o] : 0;
        __syncthreads();
        s[t] += a;
        __syncthreads();
    }
    if (t < NBLK) g_blockoff[t] = s[t] - v;
}

__global__ void __launch_bounds__(SCAN_B) k_scan3() {
    int idx = blockIdx.x * SCAN_B + threadIdx.x;
    if (idx < NN) {
        int r = g_rowptr[idx] + g_blockoff[blockIdx.x];
        g_rowptr[idx] = r;
        g_cursor[idx] = r;
    }
    if (idx == 0) g_rowptr[NN] = EE;
}

__global__ void k_fill(const int* __restrict__ ei) {
    int t = blockIdx.x * blockDim.x + threadIdx.x;
    if (t < EE) {
        int d = ei[EE + t];
        int p = atomicAdd(&g_cursor[d], 1);
        g_col[p] = ei[t];
    }
}

// ---------------------------------------------------------------------------
// Pass A: lane-per-edge gather of 16B projections; sel + selD + b1 epilogue.
// ---------------------------------------------------------------------------
__global__ void __launch_bounds__(256) k_aggA() {
    int gw = (blockIdx.x * blockDim.x + threadIdx.x) >> 5;
    int lane = threadIdx.x & 31;
    if (gw >= NN) return;
    int s = g_rowptr[gw], e = g_rowptr[gw + 1];
    float s0 = 0.f, s1 = 0.f, s2 = 0.f;
    for (int p = s + lane; p < e; p += 32) {
        int j = __ldg(&g_col[p]);                 // coalesced
        float4 ev = __ldg(&g_e[j]);               // 16B scattered
        s0 += ev.x; s1 += ev.y; s2 += ev.z;
    }
    #pragma unroll
    for (int o = 16; o; o >>= 1) {
        s0 += __shfl_xor_sync(0xffffffffu, s0, o);
        s1 += __shfl_xor_sync(0xffffffffu, s1, o);
        s2 += __shfl_xor_sync(0xffffffffu, s2, o);
    }
    if (lane == 0) {
        float r0 = fmaxf(s0, 0.f), r1 = fmaxf(s1, 0.f);
        float p1 = 1.0f / (1.0f + expf(r0 - r1));
        float sel = (p1 > THRESH) ? 1.0f : 0.0f;
        g_sel[gw]  = sel;
        g_b1[gw]   = s2;
        float d    = __ldg(&g_e[gw]).w;
        g_selD[gw] = sel * d;
    }
}

// ---------------------------------------------------------------------------
// Pass B: z = sum_j selD[j] + b1[i]; gate = sigmoid(z) * sel[i]. 4B gathers.
// ---------------------------------------------------------------------------
__global__ void __launch_bounds__(256) k_aggB() {
    int gw = (blockIdx.x * blockDim.x + threadIdx.x) >> 5;
    int lane = threadIdx.x & 31;
    if (gw >= NN) return;
    int s = g_rowptr[gw], e = g_rowptr[gw + 1];
    float z = 0.f;
    for (int p = s + lane; p < e; p += 32)
        z += __ldg(&g_selD[__ldg(&g_col[p])]);
    #pragma unroll
    for (int o = 16; o; o >>= 1) z += __shfl_xor_sync(0xffffffffu, z, o);
    if (lane == 0) {
        z += g_b1[gw];
        float ws = 1.0f / (1.0f + expf(-z));
        g_gate[gw] = ws * g_sel[gw];
    }
}

// ---------------------------------------------------------------------------
// Pass C: a_x = relu(sum gate[j]*u[j]); out = proj(expmap0(u + a_x)). fp32.
// ---------------------------------------------------------------------------
__global__ void __launch_bounds__(256) k_aggC(float* __restrict__ out) {
    int gw = (blockIdx.x * blockDim.x + threadIdx.x) >> 5;
    int lane = threadIdx.x & 31;
    if (gw >= NN) return;
    int s = g_rowptr[gw], e = g_rowptr[gw + 1];
    const u64* U = (const u64*)g_updated;
    u64 acc0 = 0, acc1 = 0;
    int p = s;
    for (; p + 4 <= e; p += 4) {
        int j0 = __ldg(&g_col[p]);
        int j1 = __ldg(&g_col[p + 1]);
        int j2 = __ldg(&g_col[p + 2]);
        int j3 = __ldg(&g_col[p + 3]);
        float g0 = __ldg(&g_gate[j0]), g1 = __ldg(&g_gate[j1]);
        float g2 = __ldg(&g_gate[j2]), g3 = __ldg(&g_gate[j3]);
        if (g0 != 0.f) acc0 = fma2(pack2(g0, g0), __ldg(&U[(size_t)j0 * 32 + lane]), acc0);
        if (g1 != 0.f) acc1 = fma2(pack2(g1, g1), __ldg(&U[(size_t)j1 * 32 + lane]), acc1);
        if (g2 != 0.f) acc0 = fma2(pack2(g2, g2), __ldg(&U[(size_t)j2 * 32 + lane]), acc0);
        if (g3 != 0.f) acc1 = fma2(pack2(g3, g3), __ldg(&U[(size_t)j3 * 32 + lane]), acc1);
    }
    for (; p < e; ++p) {
        int j = __ldg(&g_col[p]);
        float g = __ldg(&g_gate[j]);
        if (g != 0.f)
            acc0 = fma2(pack2(g, g), __ldg(&U[(size_t)j * 32 + lane]), acc0);
    }
    u64 accp = add2(acc0, acc1);
    float ax, ay; unpack2(accp, ax, ay);
    float2 ui = ((const float2*)g_updated)[(size_t)gw * 32 + lane];
    float ox = ui.x + fmaxf(ax, 0.f);
    float oy = ui.y + fmaxf(ay, 0.f);
    float ss = ox * ox + oy * oy;
    #pragma unroll
    for (int o = 16; o; o >>= 1) ss += __shfl_xor_sync(0xffffffffu, ss, o);
    float n = fmaxf(sqrtf(ss), 1e-15f);
    float th = tanhf(n);
    float f = (th > MAXN) ? (MAXN / n) : (th / n);
    ((float2*)out)[(size_t)gw * 32 + lane] = make_float2(ox * f, oy * f);
}

// ---------------------------------------------------------------------------
extern "C" void kernel_launch(void* const* d_in, const int* in_sizes, int n_in,
                              void* d_out, int out_size) {
    const float* x   = (const float*)d_in[0];
    const int*   ei  = (const int*)  d_in[1];
    const float* Wup = (const float*)d_in[2];
    const float* Wpl = (const float*)d_in[3];
    const float* Wlw = (const float*)d_in[4];
    float* out = (float*)d_out;

    (void)in_sizes; (void)n_in; (void)out_size;

    k_up<<<GEMM_BLOCKS + ZERO_BLOCKS, 256>>>(x, Wup, Wpl, Wlw);

    k_hist<<<(EE + 255) / 256, 256>>>(ei);
    k_scan1<<<NBLK, SCAN_B>>>();
    k_scan2<<<1, 128>>>();
    k_scan3<<<NBLK, SCAN_B>>>();
    k_fill<<<(EE + 255) / 256, 256>>>(ei);

    int aggBlocks = (NN * 32 + 255) / 256;
    k_aggA<<<aggBlocks, 256>>>();
    k_aggB<<<aggBlocks, 256>>>();
    k_aggC<<<aggBlocks, 256>>>(out);
}

// round 9
// speedup vs baseline: 1.2606x; 1.0419x over previous
#include <cuda_runtime.h>
#include <math.h>

#define NN   100000
#define EE   1600000
#define FIN  128
#define FOUT 64
#define THRESH 0.48f
#define MAXN   (1.0f - 4e-3f)

#define SCAN_B 1024
#define NBLK   ((NN + SCAN_B - 1) / SCAN_B)   // 98

#define GEMM_ROWS   32
#define GEMM_BLOCKS (NN / GEMM_ROWS)          // 3125
#define ZERO_BLOCKS ((NN + 255) / 256)        // 391

typedef unsigned long long u64;

// -------- scratch (device globals; no allocation allowed) --------
__device__ float  g_updated [NN * FOUT];
__device__ float4 g_e       [NN];   // (u.wpl0, u.wpl1, u.wlw_hi, u.wlw_lo)
__device__ float  g_b1      [NN];   // sum_j dot(u[j], wlw_hi)
__device__ float  g_sel     [NN];   // 0/1 hard gate
__device__ float  g_selD    [NN];   // sel * dot(u, wlw_lo)
__device__ float  g_gate    [NN];   // weight_sel * sel
__device__ int    g_rowptr  [NN + 1];
__device__ int    g_cursor  [NN];
__device__ int    g_col     [EE];
__device__ int    g_blocksum[NBLK];

// ---- f32x2 helpers ----
__device__ __forceinline__ u64 pack2(float lo, float hi) {
    u64 r; asm("mov.b64 %0,{%1,%2};" : "=l"(r) : "f"(lo), "f"(hi)); return r;
}
__device__ __forceinline__ void unpack2(u64 v, float& lo, float& hi) {
    asm("mov.b64 {%0,%1},%2;" : "=f"(lo), "=f"(hi) : "l"(v));
}
__device__ __forceinline__ u64 add2(u64 a, u64 b) {
    u64 d; asm("add.rn.f32x2 %0,%1,%2;" : "=l"(d) : "l"(a), "l"(b)); return d;
}
__device__ __forceinline__ u64 fma2(u64 a, u64 b, u64 c) {
    u64 d; asm("fma.rn.f32x2 %0,%1,%2,%3;" : "=l"(d) : "l"(a), "l"(b), "l"(c)); return d;
}

// ---------------------------------------------------------------------------
// K1: logmap0 + GEMM + leaky_relu -> g_updated; epilogue computes per-node
// projection float4 g_e. Trailing blocks zero g_cursor.
// ---------------------------------------------------------------------------
__global__ void __launch_bounds__(256) k_up(const float* __restrict__ x,
                                            const float* __restrict__ Wup,
                                            const float* __restrict__ Wpl,
                                            const float* __restrict__ Wlw) {
    if (blockIdx.x >= GEMM_BLOCKS) {
        int i = (blockIdx.x - GEMM_BLOCKS) * 256 + threadIdx.x;
        if (i < NN) g_cursor[i] = 0;
        return;
    }
    __shared__ float  xs[GEMM_ROWS][FIN];
    __shared__ float4 Ws[FIN * 16];
    __shared__ float  sscale[GEMM_ROWS];
    __shared__ float4 sWe[FOUT];     // per-col (wpl0, wpl1, wlw_hi, wlw_lo)

    int t = threadIdx.x;
    int rbase = blockIdx.x * GEMM_ROWS;

    const float4* W4 = (const float4*)Wup;
    #pragma unroll
    for (int i = t; i < FIN * 16; i += 256) Ws[i] = W4[i];
    #pragma unroll
    for (int i = t; i < GEMM_ROWS * FIN; i += 256)
        xs[i >> 7][i & 127] = x[(size_t)rbase * FIN + i];
    if (t < FOUT)
        sWe[t] = make_float4(Wpl[2 * t], Wpl[2 * t + 1], Wlw[64 + t], Wlw[t]);
    __syncthreads();

    int w = t >> 5, lane = t & 31;
    #pragma unroll
    for (int rr = 0; rr < 4; ++rr) {
        int r = w * 4 + rr;
        float v0 = xs[r][lane], v1 = xs[r][lane + 32];
        float v2 = xs[r][lane + 64], v3 = xs[r][lane + 96];
        float s = v0 * v0 + v1 * v1 + v2 * v2 + v3 * v3;
        #pragma unroll
        for (int o = 16; o; o >>= 1) s += __shfl_xor_sync(0xffffffffu, s, o);
        if (lane == 0) {
            float n = fmaxf(sqrtf(s), 1e-15f);
            float a = fminf(fmaxf(n, -1.0f + 1e-7f), 1.0f - 1e-7f);
            float art = 0.5f * (log1pf(a) - log1pf(-a));
            sscale[r] = art / n;
        }
    }
    __syncthreads();

    int rp = t >> 4;          // rows rp, rp+16
    int cg = t & 15;          // col group of 4
    int r0 = rp, r1 = rp + 16;
    u64 a00 = 0, a01 = 0, a10 = 0, a11 = 0;

    #pragma unroll 4
    for (int k = 0; k < FIN; ++k) {
        float4 wv = Ws[k * 16 + cg];
        u64 w01 = pack2(wv.x, wv.y);
        u64 w23 = pack2(wv.z, wv.w);
        float xv0 = xs[r0][k], xv1 = xs[r1][k];
        u64 xa = pack2(xv0, xv0);
        u64 xb = pack2(xv1, xv1);
        a00 = fma2(xa, w01, a00);
        a01 = fma2(xa, w23, a01);
        a10 = fma2(xb, w01, a10);
        a11 = fma2(xb, w23, a11);
    }

    float4 we0 = sWe[cg * 4 + 0], we1 = sWe[cg * 4 + 1];
    float4 we2 = sWe[cg * 4 + 2], we3 = sWe[cg * 4 + 3];

    #pragma unroll
    for (int rr = 0; rr < 2; ++rr) {
        int r = rr ? r1 : r0;
        float sc = sscale[r];
        float c0, c1, c2, c3;
        unpack2(rr ? a10 : a00, c0, c1);
        unpack2(rr ? a11 : a01, c2, c3);
        float4 o;
        float v;
        v = c0 * sc; o.x = v > 0.f ? v : 0.01f * v;
        v = c1 * sc; o.y = v > 0.f ? v : 0.01f * v;
        v = c2 * sc; o.z = v > 0.f ? v : 0.01f * v;
        v = c3 * sc; o.w = v > 0.f ? v : 0.01f * v;
        ((float4*)g_updated)[(size_t)(rbase + r) * 16 + cg] = o;

        float d0 = o.x * we0.x + o.y * we1.x + o.z * we2.x + o.w * we3.x;
        float d1 = o.x * we0.y + o.y * we1.y + o.z * we2.y + o.w * we3.y;
        float d2 = o.x * we0.z + o.y * we1.z + o.z * we2.z + o.w * we3.z;
        float d3 = o.x * we0.w + o.y * we1.w + o.z * we2.w + o.w * we3.w;
        #pragma unroll
        for (int off = 8; off; off >>= 1) {
            d0 += __shfl_xor_sync(0xffffffffu, d0, off);
            d1 += __shfl_xor_sync(0xffffffffu, d1, off);
            d2 += __shfl_xor_sync(0xffffffffu, d2, off);
            d3 += __shfl_xor_sync(0xffffffffu, d3, off);
        }
        if (cg == 0) g_e[rbase + r] = make_float4(d0, d1, d2, d3);
    }
}

// ---------------------------------------------------------------------------
// CSR build
// ---------------------------------------------------------------------------
__global__ void k_hist(const int* __restrict__ ei) {
    int t = blockIdx.x * blockDim.x + threadIdx.x;
    if (t < EE) atomicAdd(&g_cursor[ei[EE + t]], 1);
}

__global__ void __launch_bounds__(SCAN_B) k_scan1() {
    __shared__ int wsum[32];
    int t = threadIdx.x, b = blockIdx.x;
    int idx = b * SCAN_B + t;
    int lane = t & 31, w = t >> 5;
    int c = (idx < NN) ? g_cursor[idx] : 0;
    int v = c;
    #pragma unroll
    for (int o = 1; o < 32; o <<= 1) {
        int n = __shfl_up_sync(0xffffffffu, v, o);
        if (lane >= o) v += n;
    }
    if (lane == 31) wsum[w] = v;
    __syncthreads();
    if (w == 0) {
        int s = wsum[lane];
        #pragma unroll
        for (int o = 1; o < 32; o <<= 1) {
            int n = __shfl_up_sync(0xffffffffu, s, o);
            if (lane >= o) s += n;
        }
        wsum[lane] = s;
    }
    __syncthreads();
    int base = (w > 0) ? wsum[w - 1] : 0;
    int incl = v + base;
    if (idx < NN) g_rowptr[idx] = incl - c;
    if (t == SCAN_B - 1) g_blocksum[b] = incl;
}

// scan stage 2+3 merged: every block redundantly scans the 98 block sums in
// smem, then applies its own offset. One launch instead of two.
__global__ void __launch_bounds__(SCAN_B) k_scan3() {
    __shared__ int s[128];
    int t = threadIdx.x;
    if (t < 128) s[t] = (t < NBLK) ? g_blocksum[t] : 0;
    __syncthreads();
    #pragma unroll
    for (int o = 1; o < 128; o <<= 1) {
        int a = 0;
        if (t < 128 && t >= o) a = s[t - o];
        __syncthreads();
        if (t < 128) s[t] += a;
        __syncthreads();
    }
    int off = (blockIdx.x == 0) ? 0 : s[blockIdx.x - 1];
    int idx = blockIdx.x * SCAN_B + t;
    if (idx < NN) {
        int r = g_rowptr[idx] + off;
        g_rowptr[idx] = r;
        g_cursor[idx] = r;
    }
    if (idx == 0) g_rowptr[NN] = EE;
}

__global__ void k_fill(const int* __restrict__ ei) {
    int t = blockIdx.x * blockDim.x + threadIdx.x;
    if (t < EE) {
        int d = ei[EE + t];
        int p = atomicAdd(&g_cursor[d], 1);
        g_col[p] = ei[t];
    }
}

// ---------------------------------------------------------------------------
// Pass A: lane-per-edge gather of 16B projections; sel + selD + b1 epilogue.
// ---------------------------------------------------------------------------
__global__ void __launch_bounds__(256) k_aggA() {
    int gw = (blockIdx.x * blockDim.x + threadIdx.x) >> 5;
    int lane = threadIdx.x & 31;
    if (gw >= NN) return;
    int s = g_rowptr[gw], e = g_rowptr[gw + 1];
    float s0 = 0.f, s1 = 0.f, s2 = 0.f;
    for (int p = s + lane; p < e; p += 32) {
        int j = __ldg(&g_col[p]);
        float4 ev = __ldg(&g_e[j]);
        s0 += ev.x; s1 += ev.y; s2 += ev.z;
    }
    #pragma unroll
    for (int o = 16; o; o >>= 1) {
        s0 += __shfl_xor_sync(0xffffffffu, s0, o);
        s1 += __shfl_xor_sync(0xffffffffu, s1, o);
        s2 += __shfl_xor_sync(0xffffffffu, s2, o);
    }
    if (lane == 0) {
        float r0 = fmaxf(s0, 0.f), r1 = fmaxf(s1, 0.f);
        float p1 = 1.0f / (1.0f + expf(r0 - r1));
        float sel = (p1 > THRESH) ? 1.0f : 0.0f;
        g_sel[gw]  = sel;
        g_b1[gw]   = s2;
        float d    = __ldg(&g_e[gw]).w;
        g_selD[gw] = sel * d;
    }
}

// ---------------------------------------------------------------------------
// Pass B: z = sum_j selD[j] + b1[i]; gate = sigmoid(z) * sel[i]. 4B gathers.
// ---------------------------------------------------------------------------
__global__ void __launch_bounds__(256) k_aggB() {
    int gw = (blockIdx.x * blockDim.x + threadIdx.x) >> 5;
    int lane = threadIdx.x & 31;
    if (gw >= NN) return;
    int s = g_rowptr[gw], e = g_rowptr[gw + 1];
    float z = 0.f;
    for (int p = s + lane; p < e; p += 32)
        z += __ldg(&g_selD[__ldg(&g_col[p])]);
    #pragma unroll
    for (int o = 16; o; o >>= 1) z += __shfl_xor_sync(0xffffffffu, z, o);
    if (lane == 0) {
        z += g_b1[gw];
        float ws = 1.0f / (1.0f + expf(-z));
        g_gate[gw] = ws * g_sel[gw];
    }
}

// ---------------------------------------------------------------------------
// Pass C: batch-phase loads cols+gates lane-per-edge (32-wide MLP), then
// shfl-broadcast + independent U-row loads. Chain: shfl -> LDG only.
// ---------------------------------------------------------------------------
__global__ void __launch_bounds__(256) k_aggC(float* __restrict__ out) {
    int gw = (blockIdx.x * blockDim.x + threadIdx.x) >> 5;
    int lane = threadIdx.x & 31;
    if (gw >= NN) return;
    int s = g_rowptr[gw], e = g_rowptr[gw + 1];
    const u64* U = (const u64*)g_updated;
    u64 acc0 = 0, acc1 = 0;
    for (int base = s; base < e; base += 32) {
        int cnt = e - base; if (cnt > 32) cnt = 32;
        int jreg = 0; float greg = 0.f;
        if (lane < cnt) {
            jreg = __ldg(&g_col[base + lane]);        // coalesced
            greg = __ldg(&g_gate[jreg]);              // 32 scattered loads in flight
        }
        int cnt4 = (cnt + 3) & ~3;                    // pad; padded lanes have g=0
        for (int q = 0; q < cnt4; q += 4) {
            int   j0 = __shfl_sync(0xffffffffu, jreg, q);
            int   j1 = __shfl_sync(0xffffffffu, jreg, q + 1);
            int   j2 = __shfl_sync(0xffffffffu, jreg, q + 2);
            int   j3 = __shfl_sync(0xffffffffu, jreg, q + 3);
            float g0 = __shfl_sync(0xffffffffu, greg, q);
            float g1 = __shfl_sync(0xffffffffu, greg, q + 1);
            float g2 = __shfl_sync(0xffffffffu, greg, q + 2);
            float g3 = __shfl_sync(0xffffffffu, greg, q + 3);
            if (g0 != 0.f) acc0 = fma2(pack2(g0, g0), __ldg(&U[(size_t)j0 * 32 + lane]), acc0);
            if (g1 != 0.f) acc1 = fma2(pack2(g1, g1), __ldg(&U[(size_t)j1 * 32 + lane]), acc1);
            if (g2 != 0.f) acc0 = fma2(pack2(g2, g2), __ldg(&U[(size_t)j2 * 32 + lane]), acc0);
            if (g3 != 0.f) acc1 = fma2(pack2(g3, g3), __ldg(&U[(size_t)j3 * 32 + lane]), acc1);
        }
    }
    u64 accp = add2(acc0, acc1);
    float ax, ay; unpack2(accp, ax, ay);
    float2 ui = ((const float2*)g_updated)[(size_t)gw * 32 + lane];
    float ox = ui.x + fmaxf(ax, 0.f);
    float oy = ui.y + fmaxf(ay, 0.f);
    float ss = ox * ox + oy * oy;
    #pragma unroll
    for (int o = 16; o; o >>= 1) ss += __shfl_xor_sync(0xffffffffu, ss, o);
    float n = fmaxf(sqrtf(ss), 1e-15f);
    float th = tanhf(n);
    float f = (th > MAXN) ? (MAXN / n) : (th / n);
    ((float2*)out)[(size_t)gw * 32 + lane] = make_float2(ox * f, oy * f);
}

// ---------------------------------------------------------------------------
extern "C" void kernel_launch(void* const* d_in, const int* in_sizes, int n_in,
                              void* d_out, int out_size) {
    const float* x   = (const float*)d_in[0];
    const int*   ei  = (const int*)  d_in[1];
    const float* Wup = (const float*)d_in[2];
    const float* Wpl = (const float*)d_in[3];
    const float* Wlw = (const float*)d_in[4];
    float* out = (float*)d_out;

    (void)in_sizes; (void)n_in; (void)out_size;

    k_up<<<GEMM_BLOCKS + ZERO_BLOCKS, 256>>>(x, Wup, Wpl, Wlw);

    k_hist<<<(EE + 255) / 256, 256>>>(ei);
    k_scan1<<<NBLK, SCAN_B>>>();
    k_scan3<<<NBLK, SCAN_B>>>();
    k_fill<<<(EE + 255) / 256, 256>>>(ei);

    int aggBlocks = (NN * 32 + 255) / 256;
    k_aggA<<<aggBlocks, 256>>>();
    k_aggB<<<aggBlocks, 256>>>();
    k_aggC<<<aggBlocks, 256>>>(out);
}

// round 10
// speedup vs baseline: 1.4137x; 1.1214x over previous
#include <cuda_runtime.h>
#include <math.h>

#define NN   100000
#define EE   1600000
#define FIN  128
#define FOUT 64
#define THRESH 0.48f
#define MAXN   (1.0f - 4e-3f)

#define SCAN_B 1024
#define NBLK   ((NN + SCAN_B - 1) / SCAN_B)   // 98

#define GEMM_ROWS   32
#define GEMM_TPB    128
#define GEMM_BLOCKS (NN / GEMM_ROWS)               // 3125 (exact)
#define ZERO_BLOCKS ((NN + GEMM_TPB - 1) / GEMM_TPB)

typedef unsigned long long u64;

// -------- scratch (device globals; no allocation allowed) --------
__device__ float  g_updated [NN * FOUT];
__device__ float4 g_e       [NN];   // (u.wpl0, u.wpl1, u.wlw_hi, u.wlw_lo)
__device__ float  g_b1      [NN];   // sum_j dot(u[j], wlw_hi)
__device__ float  g_sel     [NN];   // 0/1 hard gate
__device__ float  g_selD    [NN];   // sel * dot(u, wlw_lo)
__device__ float  g_gate    [NN];   // weight_sel * sel
__device__ int    g_rowptr  [NN + 1];
__device__ int    g_cursor  [NN];
__device__ int    g_col     [EE];
__device__ int    g_blocksum[NBLK];

// ---- f32x2 helpers ----
__device__ __forceinline__ u64 pack2(float lo, float hi) {
    u64 r; asm("mov.b64 %0,{%1,%2};" : "=l"(r) : "f"(lo), "f"(hi)); return r;
}
__device__ __forceinline__ void unpack2(u64 v, float& lo, float& hi) {
    asm("mov.b64 {%0,%1},%2;" : "=f"(lo), "=f"(hi) : "l"(v));
}
__device__ __forceinline__ u64 add2(u64 a, u64 b) {
    u64 d; asm("add.rn.f32x2 %0,%1,%2;" : "=l"(d) : "l"(a), "l"(b)); return d;
}
__device__ __forceinline__ u64 fma2(u64 a, u64 b, u64 c) {
    u64 d; asm("fma.rn.f32x2 %0,%1,%2,%3;" : "=l"(d) : "l"(a), "l"(b), "l"(c)); return d;
}

// ---------------------------------------------------------------------------
// K1: logmap0 (applied in-place to the x tile) + GEMM + leaky_relu.
// 128 threads = 16 col-groups x 8 row-groups; 4 rows/thread halves W smem
// re-reads; x fetched via LDS.128 per 4 k. smem = 16KB xs + 32KB Ws = 48KB.
// Trailing blocks zero g_cursor.
// ---------------------------------------------------------------------------
__global__ void __launch_bounds__(GEMM_TPB) k_up(const float* __restrict__ x,
                                                 const float* __restrict__ Wup,
                                                 const float* __restrict__ Wpl,
                                                 const float* __restrict__ Wlw) {
    if (blockIdx.x >= GEMM_BLOCKS) {
        int i = (blockIdx.x - GEMM_BLOCKS) * GEMM_TPB + threadIdx.x;
        if (i < NN) g_cursor[i] = 0;
        return;
    }
    __shared__ float  xs[GEMM_ROWS][FIN];   // 16 KB
    __shared__ float4 Ws[FIN * 16];         // 32 KB  [k][16 col-groups of 4]

    int t = threadIdx.x;
    int rbase = blockIdx.x * GEMM_ROWS;

    const float4* W4 = (const float4*)Wup;
    #pragma unroll
    for (int i = t; i < FIN * 16; i += GEMM_TPB) Ws[i] = W4[i];
    const float4* x4 = (const float4*)(x + (size_t)rbase * FIN);
    float4* xs4 = (float4*)xs;
    #pragma unroll
    for (int i = t; i < GEMM_ROWS * FIN / 4; i += GEMM_TPB) xs4[i] = x4[i];
    __syncthreads();

    // logmap0 in place: warp w scales rows 8w..8w+7
    int w = t >> 5, lane = t & 31;
    #pragma unroll
    for (int rr = 0; rr < 8; ++rr) {
        int r = w * 8 + rr;
        float4 v = ((float4*)xs[r])[lane];
        float s = v.x * v.x + v.y * v.y + v.z * v.z + v.w * v.w;
        #pragma unroll
        for (int o = 16; o; o >>= 1) s += __shfl_xor_sync(0xffffffffu, s, o);
        float n = fmaxf(sqrtf(s), 1e-15f);
        float a = fminf(fmaxf(n, -1.0f + 1e-7f), 1.0f - 1e-7f);
        float art = 0.5f * (log1pf(a) - log1pf(-a));
        float sc = art / n;
        v.x *= sc; v.y *= sc; v.z *= sc; v.w *= sc;
        ((float4*)xs[r])[lane] = v;
    }
    __syncthreads();

    int cg = t & 15;          // col group (4 cols)
    int rg = t >> 4;          // 0..7; rows rg + 8*i
    u64 acc[4][2];
    #pragma unroll
    for (int i = 0; i < 4; ++i) { acc[i][0] = 0; acc[i][1] = 0; }

    #pragma unroll 2
    for (int k = 0; k < FIN; k += 4) {
        float4 xv[4];
        #pragma unroll
        for (int i = 0; i < 4; ++i)
            xv[i] = *(const float4*)&xs[rg + 8 * i][k];
        #pragma unroll
        for (int q = 0; q < 4; ++q) {
            float4 wv = Ws[(k + q) * 16 + cg];
            u64 w01 = pack2(wv.x, wv.y);
            u64 w23 = pack2(wv.z, wv.w);
            #pragma unroll
            for (int i = 0; i < 4; ++i) {
                float xq = (q == 0) ? xv[i].x : (q == 1) ? xv[i].y
                         : (q == 2) ? xv[i].z : xv[i].w;
                u64 xx = pack2(xq, xq);
                acc[i][0] = fma2(xx, w01, acc[i][0]);
                acc[i][1] = fma2(xx, w23, acc[i][1]);
            }
        }
    }

    // projection weights for this thread's 4 cols (tiny, L2/const cached)
    float4 we[4];
    #pragma unroll
    for (int m = 0; m < 4; ++m) {
        int c = cg * 4 + m;
        we[m] = make_float4(__ldg(&Wpl[2 * c]), __ldg(&Wpl[2 * c + 1]),
                            __ldg(&Wlw[64 + c]), __ldg(&Wlw[c]));
    }

    #pragma unroll
    for (int i = 0; i < 4; ++i) {
        int r = rg + 8 * i;
        float c0, c1, c2, c3;
        unpack2(acc[i][0], c0, c1);
        unpack2(acc[i][1], c2, c3);
        float4 o;
        o.x = c0 > 0.f ? c0 : 0.01f * c0;
        o.y = c1 > 0.f ? c1 : 0.01f * c1;
        o.z = c2 > 0.f ? c2 : 0.01f * c2;
        o.w = c3 > 0.f ? c3 : 0.01f * c3;
        ((float4*)g_updated)[(size_t)(rbase + r) * 16 + cg] = o;

        float d0 = o.x * we[0].x + o.y * we[1].x + o.z * we[2].x + o.w * we[3].x;
        float d1 = o.x * we[0].y + o.y * we[1].y + o.z * we[2].y + o.w * we[3].y;
        float d2 = o.x * we[0].z + o.y * we[1].z + o.z * we[2].z + o.w * we[3].z;
        float d3 = o.x * we[0].w + o.y * we[1].w + o.z * we[2].w + o.w * we[3].w;
        #pragma unroll
        for (int off = 8; off; off >>= 1) {   // reduce across the 16 cg lanes
            d0 += __shfl_xor_sync(0xffffffffu, d0, off);
            d1 += __shfl_xor_sync(0xffffffffu, d1, off);
            d2 += __shfl_xor_sync(0xffffffffu, d2, off);
            d3 += __shfl_xor_sync(0xffffffffu, d3, off);
        }
        if (cg == 0) g_e[rbase + r] = make_float4(d0, d1, d2, d3);
    }
}

// ---------------------------------------------------------------------------
// CSR build
// ---------------------------------------------------------------------------
__global__ void k_hist(const int* __restrict__ ei) {
    int t = blockIdx.x * blockDim.x + threadIdx.x;
    if (t < EE) atomicAdd(&g_cursor[ei[EE + t]], 1);
}

__global__ void __launch_bounds__(SCAN_B) k_scan1() {
    __shared__ int wsum[32];
    int t = threadIdx.x, b = blockIdx.x;
    int idx = b * SCAN_B + t;
    int lane = t & 31, w = t >> 5;
    int c = (idx < NN) ? g_cursor[idx] : 0;
    int v = c;
    #pragma unroll
    for (int o = 1; o < 32; o <<= 1) {
        int n = __shfl_up_sync(0xffffffffu, v, o);
        if (lane >= o) v += n;
    }
    if (lane == 31) wsum[w] = v;
    __syncthreads();
    if (w == 0) {
        int s = wsum[lane];
        #pragma unroll
        for (int o = 1; o < 32; o <<= 1) {
            int n = __shfl_up_sync(0xffffffffu, s, o);
            if (lane >= o) s += n;
        }
        wsum[lane] = s;
    }
    __syncthreads();
    int base = (w > 0) ? wsum[w - 1] : 0;
    int incl = v + base;
    if (idx < NN) g_rowptr[idx] = incl - c;
    if (t == SCAN_B - 1) g_blocksum[b] = incl;
}

// scan stage 2+3 merged: every block redundantly scans the 98 block sums.
__global__ void __launch_bounds__(SCAN_B) k_scan3() {
    __shared__ int s[128];
    int t = threadIdx.x;
    if (t < 128) s[t] = (t < NBLK) ? g_blocksum[t] : 0;
    __syncthreads();
    #pragma unroll
    for (int o = 1; o < 128; o <<= 1) {
        int a = 0;
        if (t < 128 && t >= o) a = s[t - o];
        __syncthreads();
        if (t < 128) s[t] += a;
        __syncthreads();
    }
    int off = (blockIdx.x == 0) ? 0 : s[blockIdx.x - 1];
    int idx = blockIdx.x * SCAN_B + t;
    if (idx < NN) {
        int r = g_rowptr[idx] + off;
        g_rowptr[idx] = r;
        g_cursor[idx] = r;
    }
    if (idx == 0) g_rowptr[NN] = EE;
}

__global__ void k_fill(const int* __restrict__ ei) {
    int t = blockIdx.x * blockDim.x + threadIdx.x;
    if (t < EE) {
        int d = ei[EE + t];
        int p = atomicAdd(&g_cursor[d], 1);
        g_col[p] = ei[t];
    }
}

// ---------------------------------------------------------------------------
// Pass A: lane-per-edge gather of 16B projections; sel + selD + b1 epilogue.
// ---------------------------------------------------------------------------
__global__ void __launch_bounds__(256) k_aggA() {
    int gw = (blockIdx.x * blockDim.x + threadIdx.x) >> 5;
    int lane = threadIdx.x & 31;
    if (gw >= NN) return;
    int s = g_rowptr[gw], e = g_rowptr[gw + 1];
    float s0 = 0.f, s1 = 0.f, s2 = 0.f;
    for (int p = s + lane; p < e; p += 32) {
        int j = __ldg(&g_col[p]);
        float4 ev = __ldg(&g_e[j]);
        s0 += ev.x; s1 += ev.y; s2 += ev.z;
    }
    #pragma unroll
    for (int o = 16; o; o >>= 1) {
        s0 += __shfl_xor_sync(0xffffffffu, s0, o);
        s1 += __shfl_xor_sync(0xffffffffu, s1, o);
        s2 += __shfl_xor_sync(0xffffffffu, s2, o);
    }
    if (lane == 0) {
        float r0 = fmaxf(s0, 0.f), r1 = fmaxf(s1, 0.f);
        float p1 = 1.0f / (1.0f + expf(r0 - r1));
        float sel = (p1 > THRESH) ? 1.0f : 0.0f;
        g_sel[gw]  = sel;
        g_b1[gw]   = s2;
        float d    = __ldg(&g_e[gw]).w;
        g_selD[gw] = sel * d;
    }
}

// ---------------------------------------------------------------------------
// Pass B: z = sum_j selD[j] + b1[i]; gate = sigmoid(z) * sel[i]. 4B gathers.
// ---------------------------------------------------------------------------
__global__ void __launch_bounds__(256) k_aggB() {
    int gw = (blockIdx.x * blockDim.x + threadIdx.x) >> 5;
    int lane = threadIdx.x & 31;
    if (gw >= NN) return;
    int s = g_rowptr[gw], e = g_rowptr[gw + 1];
    float z = 0.f;
    for (int p = s + lane; p < e; p += 32)
        z += __ldg(&g_selD[__ldg(&g_col[p])]);
    #pragma unroll
    for (int o = 16; o; o >>= 1) z += __shfl_xor_sync(0xffffffffu, z, o);
    if (lane == 0) {
        z += g_b1[gw];
        float ws = 1.0f / (1.0f + expf(-z));
        g_gate[gw] = ws * g_sel[gw];
    }
}

// ---------------------------------------------------------------------------
// Pass C: batch-phase loads cols+gates lane-per-edge, then shfl-broadcast +
// independent U-row loads.
// ---------------------------------------------------------------------------
__global__ void __launch_bounds__(256) k_aggC(float* __restrict__ out) {
    int gw = (blockIdx.x * blockDim.x + threadIdx.x) >> 5;
    int lane = threadIdx.x & 31;
    if (gw >= NN) return;
    int s = g_rowptr[gw], e = g_rowptr[gw + 1];
    const u64* U = (const u64*)g_updated;
    u64 acc0 = 0, acc1 = 0;
    for (int base = s; base < e; base += 32) {
        int cnt = e - base; if (cnt > 32) cnt = 32;
        int jreg = 0; float greg = 0.f;
        if (lane < cnt) {
            jreg = __ldg(&g_col[base + lane]);
            greg = __ldg(&g_gate[jreg]);
        }
        int cnt4 = (cnt + 3) & ~3;
        for (int q = 0; q < cnt4; q += 4) {
            int   j0 = __shfl_sync(0xffffffffu, jreg, q);
            int   j1 = __shfl_sync(0xffffffffu, jreg, q + 1);
            int   j2 = __shfl_sync(0xffffffffu, jreg, q + 2);
            int   j3 = __shfl_sync(0xffffffffu, jreg, q + 3);
            float g0 = __shfl_sync(0xffffffffu, greg, q);
            float g1 = __shfl_sync(0xffffffffu, greg, q + 1);
            float g2 = __shfl_sync(0xffffffffu, greg, q + 2);
            float g3 = __shfl_sync(0xffffffffu, greg, q + 3);
            if (g0 != 0.f) acc0 = fma2(pack2(g0, g0), __ldg(&U[(size_t)j0 * 32 + lane]), acc0);
            if (g1 != 0.f) acc1 = fma2(pack2(g1, g1), __ldg(&U[(size_t)j1 * 32 + lane]), acc1);
            if (g2 != 0.f) acc0 = fma2(pack2(g2, g2), __ldg(&U[(size_t)j2 * 32 + lane]), acc0);
            if (g3 != 0.f) acc1 = fma2(pack2(g3, g3), __ldg(&U[(size_t)j3 * 32 + lane]), acc1);
        }
    }
    u64 accp = add2(acc0, acc1);
    float ax, ay; unpack2(accp, ax, ay);
    float2 ui = ((const float2*)g_updated)[(size_t)gw * 32 + lane];
    float ox = ui.x + fmaxf(ax, 0.f);
    float oy = ui.y + fmaxf(ay, 0.f);
    float ss = ox * ox + oy * oy;
    #pragma unroll
    for (int o = 16; o; o >>= 1) ss += __shfl_xor_sync(0xffffffffu, ss, o);
    float n = fmaxf(sqrtf(ss), 1e-15f);
    float th = tanhf(n);
    float f = (th > MAXN) ? (MAXN / n) : (th / n);
    ((float2*)out)[(size_t)gw * 32 + lane] = make_float2(ox * f, oy * f);
}

// ---------------------------------------------------------------------------
extern "C" void kernel_launch(void* const* d_in, const int* in_sizes, int n_in,
                              void* d_out, int out_size) {
    const float* x   = (const float*)d_in[0];
    const int*   ei  = (const int*)  d_in[1];
    const float* Wup = (const float*)d_in[2];
    const float* Wpl = (const float*)d_in[3];
    const float* Wlw = (const float*)d_in[4];
    float* out = (float*)d_out;

    (void)in_sizes; (void)n_in; (void)out_size;

    k_up<<<GEMM_BLOCKS + ZERO_BLOCKS, GEMM_TPB>>>(x, Wup, Wpl, Wlw);

    k_hist<<<(EE + 255) / 256, 256>>>(ei);
    k_scan1<<<NBLK, SCAN_B>>>();
    k_scan3<<<NBLK, SCAN_B>>>();
    k_fill<<<(EE + 255) / 256, 256>>>(ei);

    int aggBlocks = (NN * 32 + 255) / 256;
    k_aggA<<<aggBlocks, 256>>>();
    k_aggB<<<aggBlocks, 256>>>();
    k_aggC<<<aggBlocks, 256>>>(out);
}

// round 13
// speedup vs baseline: 1.4143x; 1.0004x over previous
#include <cuda_runtime.h>
#include <math.h>

#define NN   100000
#define EE   1600000
#define FIN  128
#define FOUT 64
#define THRESH 0.48f
#define MAXN   (1.0f - 4e-3f)

#define SCAN_B 1024
#define NBLK   ((NN + SCAN_B - 1) / SCAN_B)   // 98

#define GEMM_ROWS   32
#define GEMM_TPB    128
#define GEMM_BLOCKS (NN / GEMM_ROWS)               // 3125 (exact)
#define ZERO_BLOCKS ((NN + GEMM_TPB - 1) / GEMM_TPB)

typedef unsigned long long u64;

// -------- scratch (device globals; no allocation allowed) --------
__device__ float  g_updated [NN * FOUT];
__device__ float4 g_e       [NN];   // (u.wpl0, u.wpl1, u.wlw_hi, u.wlw_lo)
__device__ float  g_b1      [NN];   // sum_j dot(u[j], wlw_hi)
__device__ float  g_sel     [NN];   // 0/1 hard gate
__device__ float  g_selD    [NN];   // sel * dot(u, wlw_lo)
__device__ float  g_gate    [NN];   // weight_sel * sel
__device__ int    g_rowptr  [NN + 1];
__device__ int    g_cursor  [NN];
__device__ int    g_col     [EE];
__device__ int    g_blocksum[NBLK];

// ---- f32x2 helpers ----
__device__ __forceinline__ u64 pack2(float lo, float hi) {
    u64 r; asm("mov.b64 %0,{%1,%2};" : "=l"(r) : "f"(lo), "f"(hi)); return r;
}
__device__ __forceinline__ void unpack2(u64 v, float& lo, float& hi) {
    asm("mov.b64 {%0,%1},%2;" : "=f"(lo), "=f"(hi) : "l"(v));
}
__device__ __forceinline__ u64 add2(u64 a, u64 b) {
    u64 d; asm("add.rn.f32x2 %0,%1,%2;" : "=l"(d) : "l"(a), "l"(b)); return d;
}
__device__ __forceinline__ u64 fma2(u64 a, u64 b, u64 c) {
    u64 d; asm("fma.rn.f32x2 %0,%1,%2,%3;" : "=l"(d) : "l"(a), "l"(b), "l"(c)); return d;
}

// ---------------------------------------------------------------------------
// K1: logmap0 (in-place on x tile) + GEMM + leaky_relu + projection epilogue.
// 128 threads = 16 col-groups x 8 row-groups; 4 rows/thread. Trailing blocks
// zero g_cursor.
// ---------------------------------------------------------------------------
__global__ void __launch_bounds__(GEMM_TPB) k_up(const float* __restrict__ x,
                                                 const float* __restrict__ Wup,
                                                 const float* __restrict__ Wpl,
                                                 const float* __restrict__ Wlw) {
    if (blockIdx.x >= GEMM_BLOCKS) {
        int i = (blockIdx.x - GEMM_BLOCKS) * GEMM_TPB + threadIdx.x;
        if (i < NN) g_cursor[i] = 0;
        return;
    }
    __shared__ float  xs[GEMM_ROWS][FIN];   // 16 KB
    __shared__ float4 Ws[FIN * 16];         // 32 KB

    int t = threadIdx.x;
    int rbase = blockIdx.x * GEMM_ROWS;

    const float4* W4 = (const float4*)Wup;
    #pragma unroll
    for (int i = t; i < FIN * 16; i += GEMM_TPB) Ws[i] = W4[i];
    const float4* x4 = (const float4*)(x + (size_t)rbase * FIN);
    float4* xs4 = (float4*)xs;
    #pragma unroll
    for (int i = t; i < GEMM_ROWS * FIN / 4; i += GEMM_TPB) xs4[i] = x4[i];
    __syncthreads();

    int w = t >> 5, lane = t & 31;
    #pragma unroll
    for (int rr = 0; rr < 8; ++rr) {
        int r = w * 8 + rr;
        float4 v = ((float4*)xs[r])[lane];
        float s = v.x * v.x + v.y * v.y + v.z * v.z + v.w * v.w;
        #pragma unroll
        for (int o = 16; o; o >>= 1) s += __shfl_xor_sync(0xffffffffu, s, o);
        float n = fmaxf(sqrtf(s), 1e-15f);
        float a = fminf(fmaxf(n, -1.0f + 1e-7f), 1.0f - 1e-7f);
        float art = 0.5f * (log1pf(a) - log1pf(-a));
        float sc = art / n;
        v.x *= sc; v.y *= sc; v.z *= sc; v.w *= sc;
        ((float4*)xs[r])[lane] = v;
    }
    __syncthreads();

    int cg = t & 15;
    int rg = t >> 4;
    u64 acc[4][2];
    #pragma unroll
    for (int i = 0; i < 4; ++i) { acc[i][0] = 0; acc[i][1] = 0; }

    #pragma unroll 2
    for (int k = 0; k < FIN; k += 4) {
        float4 xv[4];
        #pragma unroll
        for (int i = 0; i < 4; ++i)
            xv[i] = *(const float4*)&xs[rg + 8 * i][k];
        #pragma unroll
        for (int q = 0; q < 4; ++q) {
            float4 wv = Ws[(k + q) * 16 + cg];
            u64 w01 = pack2(wv.x, wv.y);
            u64 w23 = pack2(wv.z, wv.w);
            #pragma unroll
            for (int i = 0; i < 4; ++i) {
                float xq = (q == 0) ? xv[i].x : (q == 1) ? xv[i].y
                         : (q == 2) ? xv[i].z : xv[i].w;
                u64 xx = pack2(xq, xq);
                acc[i][0] = fma2(xx, w01, acc[i][0]);
                acc[i][1] = fma2(xx, w23, acc[i][1]);
            }
        }
    }

    float4 we[4];
    #pragma unroll
    for (int m = 0; m < 4; ++m) {
        int c = cg * 4 + m;
        we[m] = make_float4(__ldg(&Wpl[2 * c]), __ldg(&Wpl[2 * c + 1]),
                            __ldg(&Wlw[64 + c]), __ldg(&Wlw[c]));
    }

    #pragma unroll
    for (int i = 0; i < 4; ++i) {
        int r = rg + 8 * i;
        float c0, c1, c2, c3;
        unpack2(acc[i][0], c0, c1);
        unpack2(acc[i][1], c2, c3);
        float4 o;
        o.x = c0 > 0.f ? c0 : 0.01f * c0;
        o.y = c1 > 0.f ? c1 : 0.01f * c1;
        o.z = c2 > 0.f ? c2 : 0.01f * c2;
        o.w = c3 > 0.f ? c3 : 0.01f * c3;
        ((float4*)g_updated)[(size_t)(rbase + r) * 16 + cg] = o;

        float d0 = o.x * we[0].x + o.y * we[1].x + o.z * we[2].x + o.w * we[3].x;
        float d1 = o.x * we[0].y + o.y * we[1].y + o.z * we[2].y + o.w * we[3].y;
        float d2 = o.x * we[0].z + o.y * we[1].z + o.z * we[2].z + o.w * we[3].z;
        float d3 = o.x * we[0].w + o.y * we[1].w + o.z * we[2].w + o.w * we[3].w;
        #pragma unroll
        for (int off = 8; off; off >>= 1) {
            d0 += __shfl_xor_sync(0xffffffffu, d0, off);
            d1 += __shfl_xor_sync(0xffffffffu, d1, off);
            d2 += __shfl_xor_sync(0xffffffffu, d2, off);
            d3 += __shfl_xor_sync(0xffffffffu, d3, off);
        }
        if (cg == 0) g_e[rbase + r] = make_float4(d0, d1, d2, d3);
    }
}

// ---------------------------------------------------------------------------
// CSR build
// ---------------------------------------------------------------------------
__global__ void k_hist(const int* __restrict__ ei) {
    int t = blockIdx.x * blockDim.x + threadIdx.x;
    if (t < EE) atomicAdd(&g_cursor[ei[EE + t]], 1);
}

__global__ void __launch_bounds__(SCAN_B) k_scan1() {
    __shared__ int wsum[32];
    int t = threadIdx.x, b = blockIdx.x;
    int idx = b * SCAN_B + t;
    int lane = t & 31, w = t >> 5;
    int c = (idx < NN) ? g_cursor[idx] : 0;
    int v = c;
    #pragma unroll
    for (int o = 1; o < 32; o <<= 1) {
        int n = __shfl_up_sync(0xffffffffu, v, o);
        if (lane >= o) v += n;
    }
    if (lane == 31) wsum[w] = v;
    __syncthreads();
    if (w == 0) {
        int s = wsum[lane];
        #pragma unroll
        for (int o = 1; o < 32; o <<= 1) {
            int n = __shfl_up_sync(0xffffffffu, s, o);
            if (lane >= o) s += n;
        }
        wsum[lane] = s;
    }
    __syncthreads();
    int base = (w > 0) ? wsum[w - 1] : 0;
    int incl = v + base;
    if (idx < NN) g_rowptr[idx] = incl - c;
    if (t == SCAN_B - 1) g_blocksum[b] = incl;
}

__global__ void __launch_bounds__(SCAN_B) k_scan3() {
    __shared__ int s[128];
    int t = threadIdx.x;
    if (t < 128) s[t] = (t < NBLK) ? g_blocksum[t] : 0;
    __syncthreads();
    #pragma unroll
    for (int o = 1; o < 128; o <<= 1) {
        int a = 0;
        if (t < 128 && t >= o) a = s[t - o];
        __syncthreads();
        if (t < 128) s[t] += a;
        __syncthreads();
    }
    int off = (blockIdx.x == 0) ? 0 : s[blockIdx.x - 1];
    int idx = blockIdx.x * SCAN_B + t;
    if (idx < NN) {
        int r = g_rowptr[idx] + off;
        g_rowptr[idx] = r;
        g_cursor[idx] = r;
    }
    if (idx == 0) g_rowptr[NN] = EE;
}

__global__ void k_fill(const int* __restrict__ ei) {
    int t = blockIdx.x * blockDim.x + threadIdx.x;
    if (t < EE) {
        int d = ei[EE + t];
        int p = atomicAdd(&g_cursor[d], 1);
        g_col[p] = ei[t];
    }
}

// ---------------------------------------------------------------------------
// Pass A: lane-per-edge gather of 16B projections; sel + selD + b1 epilogue.
// ---------------------------------------------------------------------------
__global__ void __launch_bounds__(256) k_aggA() {
    int gw = (blockIdx.x * blockDim.x + threadIdx.x) >> 5;
    int lane = threadIdx.x & 31;
    if (gw >= NN) return;
    int s = g_rowptr[gw], e = g_rowptr[gw + 1];
    float s0 = 0.f, s1 = 0.f, s2 = 0.f;
    for (int p = s + lane; p < e; p += 32) {
        int j = __ldg(&g_col[p]);
        float4 ev = __ldg(&g_e[j]);
        s0 += ev.x; s1 += ev.y; s2 += ev.z;
    }
    #pragma unroll
    for (int o = 16; o; o >>= 1) {
        s0 += __shfl_xor_sync(0xffffffffu, s0, o);
        s1 += __shfl_xor_sync(0xffffffffu, s1, o);
        s2 += __shfl_xor_sync(0xffffffffu, s2, o);
    }
    if (lane == 0) {
        float r0 = fmaxf(s0, 0.f), r1 = fmaxf(s1, 0.f);
        float p1 = 1.0f / (1.0f + expf(r0 - r1));
        float sel = (p1 > THRESH) ? 1.0f : 0.0f;
        g_sel[gw]  = sel;
        g_b1[gw]   = s2;
        float d    = __ldg(&g_e[gw]).w;
        g_selD[gw] = sel * d;
    }
}

// ---------------------------------------------------------------------------
// Pass B: z = sum_j selD[j] + b1[i]; gate = sigmoid(z) * sel[i]. 4B gathers.
// ---------------------------------------------------------------------------
__global__ void __launch_bounds__(256) k_aggB() {
    int gw = (blockIdx.x * blockDim.x + threadIdx.x) >> 5;
    int lane = threadIdx.x & 31;
    if (gw >= NN) return;
    int s = g_rowptr[gw], e = g_rowptr[gw + 1];
    float z = 0.f;
    for (int p = s + lane; p < e; p += 32)
        z += __ldg(&g_selD[__ldg(&g_col[p])]);
    #pragma unroll
    for (int o = 16; o; o >>= 1) z += __shfl_xor_sync(0xffffffffu, z, o);
    if (lane == 0) {
        z += g_b1[gw];
        float ws = 1.0f / (1.0f + expf(-z));
        g_gate[gw] = ws * g_sel[gw];
    }
}

// ---------------------------------------------------------------------------
// Pass C: edge-paired. Each half-warp owns one edge; 16 lanes x float4 cover
// the 64-col row (LDG.128). Warp processes 2 edges/step: half the load
// instructions, half the shfls, half the iterations. acc halves merged by
// shfl_xor(16); only half 0 stores.
// ---------------------------------------------------------------------------
__global__ void __launch_bounds__(256) k_aggC(float* __restrict__ out) {
    int gw = (blockIdx.x * blockDim.x + threadIdx.x) >> 5;
    int lane = threadIdx.x & 31;
    if (gw >= NN) return;
    int s = g_rowptr[gw], e = g_rowptr[gw + 1];
    const float4* U4 = (const float4*)g_updated;
    int half = lane >> 4;       // which edge of the pair
    int hl   = lane & 15;       // float4 slot within the row
    u64 acc0 = 0, acc1 = 0;     // cols {4hl,4hl+1}, {4hl+2,4hl+3}

    for (int base = s; base < e; base += 32) {
        int cnt = e - base; if (cnt > 32) cnt = 32;
        int jreg = 0; float greg = 0.f;
        if (lane < cnt) {
            jreg = __ldg(&g_col[base + lane]);        // coalesced
            greg = __ldg(&g_gate[jreg]);              // 32 scattered in flight
        }
        int cnt2 = (cnt + 1) & ~1;
        for (int q = 0; q < cnt2; q += 2) {
            int myq = q + half;                       // pad slots have greg=0
            int   j = __shfl_sync(0xffffffffu, jreg, myq);
            float g = __shfl_sync(0xffffffffu, greg, myq);
            if (g != 0.f) {
                float4 u = __ldg(&U4[(size_t)j * 16 + hl]);
                u64 gg = pack2(g, g);
                acc0 = fma2(gg, pack2(u.x, u.y), acc0);
                acc1 = fma2(gg, pack2(u.z, u.w), acc1);
            }
        }
    }
    // merge the two edge-halves (same col layout in both)
    acc0 = add2(acc0, __shfl_xor_sync(0xffffffffu, acc0, 16));
    acc1 = add2(acc1, __shfl_xor_sync(0xffffffffu, acc1, 16));
    float a0, a1, a2, a3;
    unpack2(acc0, a0, a1);
    unpack2(acc1, a2, a3);

    float4 ui = __ldg(&U4[(size_t)gw * 16 + hl]);
    float o0 = ui.x + fmaxf(a0, 0.f);
    float o1 = ui.y + fmaxf(a1, 0.f);
    float o2 = ui.z + fmaxf(a2, 0.f);
    float o3 = ui.w + fmaxf(a3, 0.f);
    float ss = o0 * o0 + o1 * o1 + o2 * o2 + o3 * o3;
    // halves hold identical values; reduce within each 16-lane group
    #pragma unroll
    for (int o = 8; o; o >>= 1) ss += __shfl_xor_sync(0xffffffffu, ss, o);
    float n = fmaxf(sqrtf(ss), 1e-15f);
    float th = tanhf(n);
    float f = (th > MAXN) ? (MAXN / n) : (th / n);
    if (half == 0)
        ((float4*)out)[(size_t)gw * 16 + hl] =
            make_float4(o0 * f, o1 * f, o2 * f, o3 * f);
}

// ---------------------------------------------------------------------------
extern "C" void kernel_launch(void* const* d_in, const int* in_sizes, int n_in,
                              void* d_out, int out_size) {
    const float* x   = (const float*)d_in[0];
    const int*   ei  = (const int*)  d_in[1];
    const float* Wup = (const float*)d_in[2];
    const float* Wpl = (const float*)d_in[3];
    const float* Wlw = (const float*)d_in[4];
    float* out = (float*)d_out;

    (void)in_sizes; (void)n_in; (void)out_size;

    k_up<<<GEMM_BLOCKS + ZERO_BLOCKS, GEMM_TPB>>>(x, Wup, Wpl, Wlw);

    k_hist<<<(EE + 255) / 256, 256>>>(ei);
    k_scan1<<<NBLK, SCAN_B>>>();
    k_scan3<<<NBLK, SCAN_B>>>();
    k_fill<<<(EE + 255) / 256, 256>>>(ei);

    int aggBlocks = (NN * 32 + 255) / 256;
    k_aggA<<<aggBlocks, 256>>>();
    k_aggB<<<aggBlocks, 256>>>();
    k_aggC<<<aggBlocks, 256>>>(out);
}